// round 17
// baseline (speedup 1.0000x reference)
#include <cuda_runtime.h>
#include <cstdint>

#define NB 16
#define NT 2048
#define ND 512
#define TBLK 8             // timesteps per alphas block
#define CH 32              // pass-2 chunk length (timesteps)
#define NCH (NT / CH)      // 64 chunks
#define HALF (NT / 2)      // chain split point

// ---------------- scratch (device globals; no allocation allowed) ----------
__device__ __align__(16) float g_aT4[NT * NB];   // alphas, layout [t/4][b][4]
__device__ __align__(16) float g_Wt[NB * NT];    // per-step weight (cur), exact
__device__ __align__(16) float2 g_fire[NB * NT]; // per fire: (t as int bits, rem)
__device__ float g_integ0[NCH * NB];             // integ at chunk start
__device__ int   g_nf0[NCH * NB];                // fire count before chunk
__device__ int   g_nf[NB];                       // total fire count per batch
__device__ float g_midi[NB], g_midt[NB], g_midn[NB];  // chain state at t=HALF

// set.ge.f32 -> 1.0f/0.0f without a predicate on the dependency chain
__device__ __forceinline__ float fset_ge1(float s) {
    float r;
    asm("set.ge.f32.f32 %0, %1, 0f3F800000;" : "=f"(r) : "f"(s));
    return r;
}

__device__ __forceinline__ uint32_t smem_u32(const void* p) {
    uint32_t a;
    asm("{ .reg .u64 t; cvta.to.shared.u64 t, %1; cvt.u32.u64 %0, t; }"
        : "=r"(a) : "l"(p));
    return a;
}

__device__ __forceinline__ void mbar_wait0(uint32_t mbar) {
    asm volatile(
        "{\n\t.reg .pred P1;\n\t"
        "W%=:\n\t"
        "mbarrier.try_wait.parity.acquire.cta.shared::cta.b64 P1, [%0], 0, 0x989680;\n\t"
        "@!P1 bra W%=;\n\t}"
        :: "r"(mbar) : "memory");
}

// ---------------- kernel A: alphas (r13/r16-proven), x-offset for halves ----
// NO cudaGridDependencySynchronize inside: when launched with the PDL attr
// (A2), it runs fully concurrent with A1 — legal, the halves are independent.
__global__ __launch_bounds__(128, 8)
void alphas_kernel(const float* __restrict__ hidden,
                   const float* __restrict__ conv_w,
                   const float* __restrict__ conv_b,
                   const float* __restrict__ lin_w,
                   const float* __restrict__ lin_b,
                   float* __restrict__ alphas, int xoff) {
    __shared__ __align__(128) float sh[(TBLK + 2) * ND];   // 20KB
    __shared__ __align__(8) unsigned long long mbar;
    __shared__ float red[4][TBLK];

    const int b  = blockIdx.y;
    const int t0 = (blockIdx.x + xoff) * TBLK;

    const int gstart = (t0 == 0) ? 0 : t0 - 1;
    const int gend   = (t0 + TBLK < NT) ? t0 + TBLK : NT - 1;
    const int nrows  = gend - gstart + 1;           // 9 or 10
    const int dstrow = (t0 == 0) ? 1 : 0;

    const uint32_t mb = smem_u32(&mbar);
    if (threadIdx.x == 0) {
        asm volatile("mbarrier.init.shared.b64 [%0], 1;" :: "r"(mb) : "memory");
        const uint32_t bytes = nrows * ND * 4;
        const uint32_t dst   = smem_u32(sh) + dstrow * ND * 4;
        const float* src = hidden + (size_t)b * NT * ND + (size_t)gstart * ND;
        asm volatile("mbarrier.arrive.expect_tx.shared.b64 _, [%0], %1;"
                     :: "r"(mb), "r"(bytes) : "memory");
        asm volatile(
            "cp.async.bulk.shared::cta.global.mbarrier::complete_tx::bytes "
            "[%0], [%1], %2, [%3];"
            :: "r"(dst), "l"(src), "r"(bytes), "r"(mb) : "memory");
    }

    // weight preload — overlaps the TMA flight
    const int d = threadIdx.x * 4;
    const float4 c0 = *reinterpret_cast<const float4*>(&conv_w[d * 3]);
    const float4 c1 = *reinterpret_cast<const float4*>(&conv_w[d * 3 + 4]);
    const float4 c2 = *reinterpret_cast<const float4*>(&conv_w[d * 3 + 8]);
    const float4 w0 = make_float4(c0.x, c0.w, c1.z, c2.y);
    const float4 w1 = make_float4(c0.y + 1.f, c1.x + 1.f, c1.w + 1.f, c2.z + 1.f);
    const float4 w2 = make_float4(c0.z, c1.y, c2.x, c2.w);
    const float4 cb4 = *reinterpret_cast<const float4*>(&conv_b[d]);
    const float4 lw  = *reinterpret_cast<const float4*>(&lin_w[d]);
    const float lb   = __ldg(lin_b);

    if (t0 == 0) {
        *reinterpret_cast<float4*>(&sh[d]) = make_float4(0.f, 0.f, 0.f, 0.f);
    } else if (t0 + TBLK == NT) {
        *reinterpret_cast<float4*>(&sh[(TBLK + 1) * ND + d]) =
            make_float4(0.f, 0.f, 0.f, 0.f);
    }

    __syncthreads();        // publish mbar init (and pad rows)
    mbar_wait0(mb);

    // rolling 3-tap window over 8 timesteps, fixed d-slice
    float acc[TBLK];
    float4 hm = *reinterpret_cast<const float4*>(&sh[d]);
    float4 hc = *reinterpret_cast<const float4*>(&sh[ND + d]);
#pragma unroll
    for (int i = 0; i < TBLK; i++) {
        const float4 hp = *reinterpret_cast<const float4*>(&sh[(i + 2) * ND + d]);
        float a = 0.f, v;
        v = fmaf(hm.x, w0.x, fmaf(hc.x, w1.x, fmaf(hp.x, w2.x, cb4.x)));
        a = fmaf(fmaxf(v, 0.f), lw.x, a);
        v = fmaf(hm.y, w0.y, fmaf(hc.y, w1.y, fmaf(hp.y, w2.y, cb4.y)));
        a = fmaf(fmaxf(v, 0.f), lw.y, a);
        v = fmaf(hm.z, w0.z, fmaf(hc.z, w1.z, fmaf(hp.z, w2.z, cb4.z)));
        a = fmaf(fmaxf(v, 0.f), lw.z, a);
        v = fmaf(hm.w, w0.w, fmaf(hc.w, w1.w, fmaf(hp.w, w2.w, cb4.w)));
        a = fmaf(fmaxf(v, 0.f), lw.w, a);
        acc[i] = a;
        hm = hc; hc = hp;
    }

#pragma unroll
    for (int o = 16; o > 0; o >>= 1) {
#pragma unroll
        for (int i = 0; i < TBLK; i++)
            acc[i] += __shfl_xor_sync(0xffffffffu, acc[i], o);
    }
    const int warp = threadIdx.x >> 5;
    if ((threadIdx.x & 31) == 0) {
#pragma unroll
        for (int i = 0; i < TBLK; i++) red[warp][i] = acc[i];
    }
    __syncthreads();

    if (threadIdx.x < TBLK) {
        const int i = threadIdx.x;
        const float s = ((red[0][i] + red[1][i]) + (red[2][i] + red[3][i])) + lb;
        const float sg = 1.0f / (1.0f + __expf(-s));
        const int t = t0 + i;
        alphas[b * NT + t] = sg;
        g_aT4[((t >> 2) * NB + b) * 4 + (t & 3)] = sg;
    }
}

// ---------------- kernel B1: sequential chain, split halves ----------------
// FIRST=1: steps [0,HALF), saves state; runs on a HIGH-PRIORITY side stream
// concurrent with A2 (its single block jumps the dispatch queue).
// FIRST=0: resumes state, steps [HALF,NT). Identical op sequence => bit-exact.
template <int FIRST>
__global__ void scan_pass1_part(float* __restrict__ token_num) {
#if __CUDA_ARCH__ >= 900
    if (!FIRST) cudaGridDependencySynchronize();   // PDL: wait A2 (stream pred)
#endif
    const int b = threadIdx.x;
    if (b >= NB) return;

    const int T0 = FIRST ? 0 : HALF;
    const int T1 = FIRST ? HALF : NT;
    const float4* ap = reinterpret_cast<const float4*>(g_aT4) + b;

    float integ, tn, nfF;
    if (FIRST) { integ = 0.f; tn = 0.f; nfF = 0.f; }
    else       { integ = g_midi[b]; tn = g_midt[b]; nfF = g_midn[b]; }

    float4 buf_cur[8], buf_nxt[8];
#pragma unroll
    for (int k = 0; k < 8; k++) buf_cur[k] = ap[((T0 >> 2) + k) * NB];

    for (int t0 = T0; t0 < T1; t0 += CH) {
        g_integ0[(t0 >> 5) * NB + b] = integ;
        g_nf0[(t0 >> 5) * NB + b]   = (int)nfF;
        if (t0 + CH < T1) {
#pragma unroll
            for (int k = 0; k < 8; k++) buf_nxt[k] = ap[((t0 >> 2) + 8 + k) * NB];
        }
#pragma unroll
        for (int k = 0; k < 8; k++) {
            float a4[4] = {buf_cur[k].x, buf_cur[k].y, buf_cur[k].z, buf_cur[k].w};
#pragma unroll
            for (int i = 0; i < 4; i++) {
                const float a   = a4[i];
                const float s   = integ + a;     // chain: FADD
                const float sel = fset_ge1(s);   // chain: FSET (1.0/0.0, no pred)
                nfF += sel;                      // off-chain
                tn  += a;                        // off-chain
                integ = s - sel;                 // chain: FADD (== s-1.0f at fires)
            }
        }
#pragma unroll
        for (int k = 0; k < 8; k++) buf_cur[k] = buf_nxt[k];
    }
    if (FIRST) { g_midi[b] = integ; g_midt[b] = tn; g_midn[b] = nfF; }
    else       { g_nf[b] = (int)nfF; token_num[b] = tn; }
}

// ---------------- kernel B2: parallel chunk replay (pass 2, PDL) -----------
__global__ void scan_pass2(float* __restrict__ fires) {
    cudaGridDependencySynchronize();    // PDL: wait for pass1b (and chain)
    const int c = blockIdx.x;
    const int b = threadIdx.x;
    if (b >= NB) return;

    float integ = g_integ0[c * NB + b];
    int nf      = g_nf0[c * NB + b];
    const int tbase = c * CH;
    const float4* ap = reinterpret_cast<const float4*>(g_aT4) + b;
    float*  fb = fires + b * NT;
    float*  wb = g_Wt + b * NT;
    float2* pb = g_fire + b * NT;

#pragma unroll
    for (int k = 0; k < 8; k++) {
        const float4 av = ap[((tbase >> 2) + k) * NB];
        float a4[4] = {av.x, av.y, av.z, av.w};
        float4 fout, wout;
#pragma unroll
        for (int i = 0; i < 4; i++) {
            const float a    = a4[i];
            const float dist = 1.0f - integ;
            const float s    = integ + a;
            const bool fire  = (s >= 1.0f);
            const float cur  = fire ? dist : a;
            ((float*)&fout)[i] = s;
            ((float*)&wout)[i] = cur;
            const float rem = a - cur;
            if (fire) pb[nf] = make_float2(__int_as_float(tbase + k * 4 + i), rem);
            nf += fire ? 1 : 0;
            integ = fire ? (s - 1.0f) : s;
        }
        const int t = tbase + k * 4;
        *reinterpret_cast<float4*>(fb + t) = fout;
        *reinterpret_cast<float4*>(wb + t) = wout;
    }
}

// ---------------- kernel C: segmented gather (r16-proven) -------------------
__global__ void gather_kernel(const float* __restrict__ hidden,
                              float* __restrict__ acoustic, int ML) {
    cudaGridDependencySynchronize();    // PDL: wait for pass2 outputs
    const int r = gridDim.x - 1 - blockIdx.x;       // hot rows first
    const int b = blockIdx.y;
    const int d = threadIdx.x * 4;

    // flat prologue: all three loads issue in parallel
    const int   nf = g_nf[b];
    const float2 fc = g_fire[b * NT + (r < NT ? r : NT - 1)];
    const float2 fp = g_fire[b * NT + (r > 0 ? r - 1 : 0)];

    float4 acc = make_float4(0.f, 0.f, 0.f, 0.f);
    if (r < nf) {
        const float* hb = hidden + (size_t)b * NT * ND + d;
        const int end   = __float_as_int(fc.x);
        int start = 0;
        if (r > 0) {
            const int ps    = __float_as_int(fp.x);
            const float rem = fp.y;
            const float4 h  = *reinterpret_cast<const float4*>(hb + (size_t)ps * ND);
            acc.x = rem * h.x; acc.y = rem * h.y;
            acc.z = rem * h.z; acc.w = rem * h.w;
            start = ps + 1;
        }
        for (int t = start; t <= end; t++) {
            const float w  = g_Wt[b * NT + t];
            const float4 h = *reinterpret_cast<const float4*>(hb + (size_t)t * ND);
            acc.x = fmaf(w, h.x, acc.x); acc.y = fmaf(w, h.y, acc.y);
            acc.z = fmaf(w, h.z, acc.z); acc.w = fmaf(w, h.w, acc.w);
        }
    }
    *reinterpret_cast<float4*>(&acoustic[((size_t)b * ML + r) * ND + d]) = acc;
}

// ---------------- launch: priority-stream overlap + PDL chain ---------------
// A1 -> evA1 -> { A2 (PDL, concurrent with A1 tail) || s2(hi-prio): pass1a }
// -> pass1b (waits evP + A2) -> pass2 (PDL) -> gather (PDL)
extern "C" void kernel_launch(void* const* d_in, const int* in_sizes, int n_in,
                              void* d_out, int out_size) {
    const float* hidden = (const float*)d_in[0];
    const float* conv_w = (const float*)d_in[1];
    const float* conv_b = (const float*)d_in[2];
    const float* lin_w  = (const float*)d_in[3];
    const float* lin_b  = (const float*)d_in[4];
    float* out = (float*)d_out;

    const int ML = (out_size - NB - 2 * NB * NT) / (NB * ND);
    float* acoustic  = out;
    float* token_num = out + (size_t)NB * ML * ND;
    float* alphas    = token_num + NB;
    float* fires     = alphas + NB * NT;

    static cudaStream_t s2 = nullptr;
    static cudaEvent_t evA1 = nullptr, evP = nullptr;
    if (s2 == nullptr) {
        int lo, hi;
        cudaDeviceGetStreamPriorityRange(&lo, &hi);
        cudaStreamCreateWithPriority(&s2, cudaStreamNonBlocking, hi);
        cudaEventCreateWithFlags(&evA1, cudaEventDisableTiming);
        cudaEventCreateWithFlags(&evP, cudaEventDisableTiming);
    }

    cudaLaunchAttribute attrs[1];
    attrs[0].id = cudaLaunchAttributeProgrammaticStreamSerialization;
    attrs[0].val.programmaticStreamSerializationAllowed = 1;

    const int HB = HALF / TBLK;     // 128 blocks per batch per half

    // A1: first half of alphas
    alphas_kernel<<<dim3(HB, NB), 128>>>(hidden, conv_w, conv_b,
                                         lin_w, lin_b, alphas, 0);
    cudaEventRecord(evA1, 0);

    // A2: second half — PDL attr, no grid-sync inside => concurrent with A1 tail
    {
        cudaLaunchConfig_t cfg = {};
        cfg.gridDim = dim3(HB, NB, 1);
        cfg.blockDim = dim3(128, 1, 1);
        cfg.attrs = attrs; cfg.numAttrs = 1;
        cudaLaunchKernelEx(&cfg, alphas_kernel, hidden, conv_w, conv_b,
                           lin_w, lin_b, alphas, HB);
    }

    // side stream (HIGH PRIORITY): chain over first half, overlapped with A2
    cudaStreamWaitEvent(s2, evA1, 0);
    scan_pass1_part<1><<<1, 32, 0, s2>>>(token_num);
    cudaEventRecord(evP, s2);

    // main: resume chain (needs A2 via PDL grid-sync + pass1a via evP)
    cudaStreamWaitEvent(0, evP, 0);
    {
        cudaLaunchConfig_t cfg = {};
        cfg.gridDim = dim3(1, 1, 1);
        cfg.blockDim = dim3(32, 1, 1);
        cfg.attrs = attrs; cfg.numAttrs = 1;
        cudaLaunchKernelEx(&cfg, scan_pass1_part<0>, token_num);
    }
    {
        cudaLaunchConfig_t cfg = {};
        cfg.gridDim = dim3(NCH, 1, 1);
        cfg.blockDim = dim3(32, 1, 1);
        cfg.attrs = attrs; cfg.numAttrs = 1;
        cudaLaunchKernelEx(&cfg, scan_pass2, fires);
    }
    if (ML > 0) {
        cudaLaunchConfig_t cfg = {};
        cfg.gridDim = dim3(ML, NB, 1);
        cfg.blockDim = dim3(ND / 4, 1, 1);
        cfg.attrs = attrs; cfg.numAttrs = 1;
        cudaLaunchKernelEx(&cfg, gather_kernel, hidden, acoustic, ML);
    }
}